// round 17
// baseline (speedup 1.0000x reference)
#include <cuda_runtime.h>
#include <cuda_bf16.h>
#include <cuda_fp16.h>
#include <cstdint>
#include <math.h>

#define HW 128
#define NB 4
#define C_ 128
#define NHEADS 4
#define NO 324                 // 81 * heads (reference layout)
#define NOP 384                // padded to 24 x 16
#define NPIX (NB * HW * HW)    // 65536
#define ATTS 48                // att halves per pixel: [h][py*4+px]

// ============================ PTX helpers (baseline ISA only) ===============
__device__ __forceinline__ uint32_t smem_u32(const void* p) {
    uint32_t a;
    asm("{ .reg .u64 t; cvta.to.shared.u64 t, %1; cvt.u32.u64 %0, t; }" : "=r"(a) : "l"(p));
    return a;
}

#define LDSM_X4(r0, r1, r2, r3, addr)                                           \
    asm volatile("ldmatrix.sync.aligned.m8n8.x4.shared.b16 {%0,%1,%2,%3}, [%4];" \
                 : "=r"(r0), "=r"(r1), "=r"(r2), "=r"(r3) : "r"(addr))

#define MMA_F16(d, a, b0v, b1v)                                                 \
    asm volatile("mma.sync.aligned.m16n8k16.row.col.f32.f16.f16.f32 "           \
                 "{%0,%1,%2,%3}, {%4,%5,%6,%7}, {%8,%9}, {%0,%1,%2,%3};"        \
                 : "+f"((d)[0]), "+f"((d)[1]), "+f"((d)[2]), "+f"((d)[3])       \
                 : "r"((a)[0]), "r"((a)[1]), "r"((a)[2]), "r"((a)[3]),          \
                   "r"(b0v), "r"(b1v))

#define CP_ASYNC16(dst, src)                                                    \
    asm volatile("cp.async.cg.shared.global [%0], [%1], 16;" :: "r"(dst), "l"(src))
#define CP_ASYNC16_Z(dst, src, n)                                               \
    asm volatile("cp.async.cg.shared.global [%0], [%1], 16, %2;"                \
                 :: "r"(dst), "l"(src), "r"(n))
#define CP_ASYNC8_Z(dst, src, n)                                                \
    asm volatile("cp.async.ca.shared.global [%0], [%1], 8, %2;"                 \
                 :: "r"(dst), "l"(src), "r"(n))
#define CP_COMMIT()  asm volatile("cp.async.commit_group;" ::: "memory")
#define CP_WAIT0()   asm volatile("cp.async.wait_group 0;" ::: "memory")
#define CP_WAIT1()   asm volatile("cp.async.wait_group 1;" ::: "memory")

__device__ __forceinline__ uint32_t pack_half2(float a, float b) {
    __half2 t = __float22half2_rn(make_float2(a, b));
    return *reinterpret_cast<uint32_t*>(&t);
}

// ============================ scratch globals ================================
__device__ __align__(128) __half g_atth[(size_t)9 * NPIX * ATTS]; // [q][pix][h][py*4+px]
__device__ __align__(128) __half g_Uh[(size_t)9 * NPIX * C_];     // fp16 U
__device__ __align__(128) __half g_xh[(size_t)NPIX * C_];
__device__ __align__(128) __half g_wvh[9 * C_ * C_];
__device__ __align__(128) __half g_wqh[NOP * C_];
__device__ __align__(128) __half g_yf[(size_t)NPIX * C_];
__device__ __align__(128) __half g_wph[C_ * C_];

// ============================ merged cvt kernel ==============================
#define NX  (NPIX * C_)
#define NWV (9 * C_ * C_)
#define NWP (C_ * C_)
#define NWQ (NOP * C_)
__global__ __launch_bounds__(256) void cvt_all_kernel(const float* __restrict__ x,
                                                      const float* __restrict__ wv,
                                                      const float* __restrict__ wp,
                                                      const float* __restrict__ wq) {
    int i = blockIdx.x * 256 + threadIdx.x;
    if (i < NX) {
        g_xh[i] = __float2half_rn(x[i]);
    } else if (i < NX + NWV) {
        int j = i - NX;
        g_wvh[j] = __float2half_rn(wv[j]);
    } else if (i < NX + NWV + NWP) {
        int j = i - NX - NWV;
        g_wph[j] = __float2half_rn(wp[j]);
    } else if (i < NX + NWV + NWP + NWQ) {
        int j = i - NX - NWV - NWP;
        g_wqh[j] = __float2half_rn((j < NO * C_) ? wq[j] : 0.f);
    }
}

// ---- K1: att = softmax(x @ w_qkv^T) FUSED (fp16 mma + in-smem softmax) -----
#define RAWS 388   // raw smem row stride (floats); 1552B, 16B-aligned
__global__ __launch_bounds__(256, 1) void gemm_att_f16() {
    extern __shared__ char smem[];
    const uint32_t sb = smem_u32(smem);
    constexpr int BOF = 16384;

    const int tid = threadIdx.x, wid = tid >> 5, lane = tid & 31;
    const int lr = lane & 7, grp = lane >> 3;
    const int mbase = blockIdx.x * 64;
    const int m0 = (wid & 1) * 32, n0 = (wid >> 1) * 96;

    for (int it = tid; it < 1024; it += 256) {
        int r = it >> 4, c = it & 15;
        uint32_t off = (uint32_t)r * 256 + ((uint32_t)(c ^ (r & 7)) << 4);
        CP_ASYNC16(sb + off, (const void*)(g_xh + (size_t)(mbase + r) * C_ + c * 8));
    }
    for (int it = tid; it < 6144; it += 256) {
        int r = it >> 4, c = it & 15;
        uint32_t off = (uint32_t)r * 256 + ((uint32_t)(c ^ (r & 7)) << 4);
        CP_ASYNC16(sb + BOF + off, (const void*)(g_wqh + (size_t)r * C_ + c * 8));
    }
    CP_COMMIT();
    CP_WAIT0();
    __syncthreads();

    const int rowA0 = m0 + (grp & 1) * 8 + lr;
    const int rowB0 = n0 + (grp >> 1) * 8 + lr;
    const int chA = grp >> 1;
    const int chB = grp & 1;

    float acc[2][12][4];
#pragma unroll
    for (int mt = 0; mt < 2; mt++)
#pragma unroll
        for (int nt = 0; nt < 12; nt++)
#pragma unroll
            for (int j = 0; j < 4; j++) acc[mt][nt][j] = 0.f;

#pragma unroll
    for (int ks = 0; ks < 8; ks++) {
        const int kc = ks * 2;
        uint32_t a[2][4];
#pragma unroll
        for (int mt = 0; mt < 2; mt++) {
            int row = rowA0 + mt * 16, ch = kc + chA;
            uint32_t ad = sb + (uint32_t)row * 256 + ((uint32_t)(ch ^ (row & 7)) << 4);
            LDSM_X4(a[mt][0], a[mt][1], a[mt][2], a[mt][3], ad);
        }
        uint32_t b[6][4];
#pragma unroll
        for (int np = 0; np < 6; np++) {
            int row = rowB0 + np * 16, ch = kc + chB;
            uint32_t bd = sb + BOF + (uint32_t)row * 256 + ((uint32_t)(ch ^ (row & 7)) << 4);
            LDSM_X4(b[np][0], b[np][1], b[np][2], b[np][3], bd);
        }
#pragma unroll
        for (int mt = 0; mt < 2; mt++)
#pragma unroll
            for (int nt = 0; nt < 12; nt++)
                MMA_F16(acc[mt][nt], a[mt],
                        b[nt >> 1][(nt & 1) * 2], b[nt >> 1][(nt & 1) * 2 + 1]);
    }

    __syncthreads();
    float* raw = (float*)(smem + BOF);
#pragma unroll
    for (int mt = 0; mt < 2; mt++) {
        int r0 = m0 + mt * 16 + (lane >> 2);
#pragma unroll
        for (int nt = 0; nt < 12; nt++) {
            int c0 = n0 + nt * 8 + (lane & 3) * 2;
            *(float2*)&raw[(size_t)r0 * RAWS + c0] =
                make_float2(acc[mt][nt][0], acc[mt][nt][1]);
            *(float2*)&raw[(size_t)(r0 + 8) * RAWS + c0] =
                make_float2(acc[mt][nt][2], acc[mt][nt][3]);
        }
    }
    __syncthreads();

    const float scale = 0.17677669529663687f;  // 32^-0.5
    for (int idx = tid; idx < 64 * 36; idx += 256) {
        int pix = idx / 36, hp = idx % 36;
        int h = hp / 9, p = hp % 9;
        const float* r = &raw[(size_t)pix * RAWS + h * 81 + p * 9];
        float m = r[0];
#pragma unroll
        for (int q = 1; q < 9; q++) m = fmaxf(m, r[q]);
        float e[9], ssum = 0.f;
#pragma unroll
        for (int q = 0; q < 9; q++) {
            float u = (r[q] - m) * scale;
            float t = fmaf(u, 1.38888889e-3f, 8.33333333e-3f);
            t = fmaf(t, u, 4.16666667e-2f);
            t = fmaf(t, u, 1.66666667e-1f);
            t = fmaf(t, u, 0.5f);
            t = fmaf(t, u, 1.0f);
            t = fmaf(t, u, 1.0f);
            e[q] = t;
            ssum += t;
        }
        float inv = __frcp_rn(ssum);
        // layout: [q][pix][h][ (p/3)*4 + p%3 ], ATTS=48 halves per pixel
        int pp = (p / 3) * 4 + (p % 3);
        __half* dst = g_atth + (size_t)(mbase + pix) * ATTS + h * 12 + pp;
#pragma unroll
        for (int q = 0; q < 9; q++)
            dst[(size_t)q * NPIX * ATTS] = __float2half_rn(e[q] * inv);
    }
}

// ---- K2: U_q = x @ w_v[q]^T via fp16 mma, double-buffered B, fp16 out -------
__global__ __launch_bounds__(256, 2) void gemm_val_f16() {
    extern __shared__ char smem[];
    const uint32_t sb = smem_u32(smem);
    constexpr int BST = 32768;

    const int tid = threadIdx.x, wid = tid >> 5, lane = tid & 31;
    const int lr = lane & 7, grp = lane >> 3;
    const int mbase = blockIdx.x * 128;
    const int m0 = (wid & 3) * 32, n0 = (wid >> 2) * 64;

    for (int it = tid; it < 2048; it += 256) {
        int r = it >> 4, c = it & 15;
        uint32_t off = (uint32_t)r * 256 + ((uint32_t)(c ^ (r & 7)) << 4);
        CP_ASYNC16(sb + off, (const void*)(g_xh + (size_t)(mbase + r) * C_ + c * 8));
        CP_ASYNC16(sb + BST + off, (const void*)(g_wvh + (size_t)r * C_ + c * 8));
    }
    CP_COMMIT();
    for (int it = tid; it < 2048; it += 256) {
        int r = it >> 4, c = it & 15;
        uint32_t off = (uint32_t)r * 256 + ((uint32_t)(c ^ (r & 7)) << 4);
        CP_ASYNC16(sb + BST + 32768 + off, (const void*)(g_wvh + ((size_t)C_ + r) * C_ + c * 8));
    }
    CP_COMMIT();

    const int rowA0 = m0 + (grp & 1) * 8 + lr;
    const int rowB0 = n0 + (grp >> 1) * 8 + lr;
    const int chA = grp >> 1;
    const int chB = grp & 1;

    for (int q = 0; q < 9; q++) {
        const uint32_t bst = sb + BST + (uint32_t)(q & 1) * 32768;
        CP_WAIT1();
        __syncthreads();

        float acc[2][8][4];
#pragma unroll
        for (int mt = 0; mt < 2; mt++)
#pragma unroll
            for (int nt = 0; nt < 8; nt++)
#pragma unroll
                for (int j = 0; j < 4; j++) acc[mt][nt][j] = 0.f;

#pragma unroll
        for (int ks = 0; ks < 8; ks++) {
            const int kc = ks * 2;
            uint32_t a[2][4];
#pragma unroll
            for (int mt = 0; mt < 2; mt++) {
                int row = rowA0 + mt * 16, ch = kc + chA;
                uint32_t ad = sb + (uint32_t)row * 256 + ((uint32_t)(ch ^ (row & 7)) << 4);
                LDSM_X4(a[mt][0], a[mt][1], a[mt][2], a[mt][3], ad);
            }
            uint32_t b[4][4];
#pragma unroll
            for (int np = 0; np < 4; np++) {
                int row = rowB0 + np * 16, ch = kc + chB;
                uint32_t bd = bst + (uint32_t)row * 256 + ((uint32_t)(ch ^ (row & 7)) << 4);
                LDSM_X4(b[np][0], b[np][1], b[np][2], b[np][3], bd);
            }
#pragma unroll
            for (int mt = 0; mt < 2; mt++)
#pragma unroll
                for (int nt = 0; nt < 8; nt++)
                    MMA_F16(acc[mt][nt], a[mt],
                            b[nt >> 1][(nt & 1) * 2], b[nt >> 1][(nt & 1) * 2 + 1]);
        }
        __syncthreads();

        if (q + 2 < 9) {
            for (int it = tid; it < 2048; it += 256) {
                int r = it >> 4, c = it & 15;
                uint32_t off = (uint32_t)r * 256 + ((uint32_t)(c ^ (r & 7)) << 4);
                CP_ASYNC16(bst + off, (const void*)(g_wvh + ((size_t)(q + 2) * C_ + r) * C_ + c * 8));
            }
        }
        CP_COMMIT();

        __half* op = g_Uh + (size_t)q * NPIX * C_;
#pragma unroll
        for (int mt = 0; mt < 2; mt++) {
            int r0 = mbase + m0 + mt * 16 + (lane >> 2);
#pragma unroll
            for (int nt = 0; nt < 8; nt++) {
                int c0 = n0 + nt * 8 + (lane & 3) * 2;
                *(uint32_t*)(op + (size_t)r0 * C_ + c0) =
                    pack_half2(acc[mt][nt][0], acc[mt][nt][1]);
                *(uint32_t*)(op + (size_t)(r0 + 8) * C_ + c0) =
                    pack_half2(acc[mt][nt][2], acc[mt][nt][3]);
            }
        }
    }
}

// ---- K3: fold, double-buffered cp.async, HFMA2, LDS.64 att ------------------
// SMEM: U0 25600 | U1 25600 | A0 9600 | A1 9600  = 70400 B
__global__ __launch_bounds__(256) void fold_kernel() {
    extern __shared__ char fsm[];
    const uint32_t sb = smem_u32(fsm);
    constexpr int U1 = 25600, A0 = 51200, A1 = 60800;

    const int tid = threadIdx.x;
    const int blk = blockIdx.x;
    const int b  = blk >> 8;
    const int ti = blk & 255;
    const int ty0 = (ti >> 4) * 8, tx0 = (ti & 15) * 8;
    const int cg = tid & 31;        // channel quad
    const int cl = tid >> 5;        // output row ny
    const int h12 = (cg >> 3) * 12; // head offset into att row (halves)

    auto fill = [&](int q, uint32_t ubuf, uint32_t abuf) {
        const int dy = q / 3 - 1, dx = q % 3 - 1;
        // U window: 100 px x 256B = 1600 16B chunks
        for (int idx = tid; idx < 1600; idx += 256) {
            int m = idx >> 4, c = idx & 15;
            int wy = m / 10, wx = m % 10;
            int iy = ty0 - 1 + dy + wy, ix = tx0 - 1 + dx + wx;
            bool ok = (iy >= 0 && iy < HW && ix >= 0 && ix < HW);
            const __half* src = g_Uh + ((size_t)q * NPIX
                    + (size_t)(b * HW + (ok ? iy : 0)) * HW + (ok ? ix : 0)) * C_ + c * 8;
            CP_ASYNC16_Z(ubuf + (uint32_t)m * 256 + c * 16, (const void*)src,
                         ok ? 16u : 0u);
        }
        // att halo: 100 px x 96B = 1200 8B chunks
        for (int idx = tid; idx < 1200; idx += 256) {
            int m = idx / 12, c = idx % 12;
            int wy = m / 10, wx = m % 10;
            int iy = ty0 - 1 + wy, ix = tx0 - 1 + wx;
            bool ok = (iy >= 0 && iy < HW && ix >= 0 && ix < HW);
            const __half* src = g_atth + ((size_t)q * NPIX
                    + (size_t)(b * HW + (ok ? iy : 0)) * HW + (ok ? ix : 0)) * ATTS + c * 4;
            CP_ASYNC8_Z(abuf + (uint32_t)m * 96 + c * 8, (const void*)src,
                        ok ? 8u : 0u);
        }
    };

    fill(0, sb, sb + A0);
    CP_COMMIT();
    fill(1, sb + U1, sb + A1);
    CP_COMMIT();

    float acc[8][4];
#pragma unroll
    for (int nx = 0; nx < 8; nx++)
#pragma unroll
        for (int j = 0; j < 4; j++) acc[nx][j] = 0.f;

    for (int q = 0; q < 9; q++) {
        const uint32_t ub = sb + (uint32_t)(q & 1) * U1;
        const uint32_t ab = sb + A0 + (uint32_t)(q & 1) * 9600;
        CP_WAIT1();
        __syncthreads();

        const __half* u_sh   = (const __half*)(fsm + (ub - sb));
        const __half* att_sh = (const __half*)(fsm + (ab - sb));

        __half2 aq[8][2];
#pragma unroll
        for (int nx = 0; nx < 8; nx++) {
            aq[nx][0] = __float2half2_rn(0.f);
            aq[nx][1] = __float2half2_rn(0.f);
        }

#pragma unroll
        for (int py = 0; py < 3; py++) {
            const int hy = cl + 2 - py;
#pragma unroll
            for (int hx = 0; hx < 10; hx++) {
                const int m = hy * 10 + hx;
                uint2 uraw = *(const uint2*)(u_sh + m * 128 + cg * 4);
                __half2 u0 = *reinterpret_cast<__half2*>(&uraw.x);
                __half2 u1 = *reinterpret_cast<__half2*>(&uraw.y);
                // one LDS.64: att for (h, py, px=0..2) (+pad)
                uint2 araw = *(const uint2*)(att_sh + m * 48 + h12 + py * 4);
                __half2 a01 = *reinterpret_cast<__half2*>(&araw.x);
                __half2 a2x = *reinterpret_cast<__half2*>(&araw.y);
#pragma unroll
                for (int px = 0; px < 3; px++) {
                    const int nx = hx - 2 + px;
                    if (nx >= 0 && nx < 8) {
                        __half av = (px == 0) ? __low2half(a01)
                                  : (px == 1) ? __high2half(a01)
                                              : __low2half(a2x);
                        __half2 aa = __half2half2(av);
                        aq[nx][0] = __hfma2(aa, u0, aq[nx][0]);
                        aq[nx][1] = __hfma2(aa, u1, aq[nx][1]);
                    }
                }
            }
        }

#pragma unroll
        for (int nx = 0; nx < 8; nx++) {
            float2 f0 = __half22float2(aq[nx][0]);
            float2 f1 = __half22float2(aq[nx][1]);
            acc[nx][0] += f0.x;
            acc[nx][1] += f0.y;
            acc[nx][2] += f1.x;
            acc[nx][3] += f1.y;
        }
        __syncthreads();

        if (q + 2 < 9)
            fill(q + 2, ub, ab);
        CP_COMMIT();
    }

#pragma unroll
    for (int nx = 0; nx < 8; nx++) {
        size_t pix = (size_t)(b * HW + ty0 + cl) * HW + (tx0 + nx);
        uint2 pk;
        pk.x = pack_half2(acc[nx][0], acc[nx][1]);
        pk.y = pack_half2(acc[nx][2], acc[nx][3]);
        *(uint2*)(g_yf + pix * C_ + cg * 4) = pk;
    }
}

// ---- K4: projection, single-pass fp16 mma -----------------------------------
__global__ __launch_bounds__(256, 2) void gemm_proj_f16(float* __restrict__ out0) {
    extern __shared__ char smem[];
    const uint32_t sb = smem_u32(smem);
    constexpr int BOF = 32768;

    const int tid = threadIdx.x, wid = tid >> 5, lane = tid & 31;
    const int lr = lane & 7, grp = lane >> 3;
    const int mbase = blockIdx.x * 128;
    const int m0 = (wid & 3) * 32, n0 = (wid >> 2) * 64;

    for (int it = tid; it < 2048; it += 256) {
        int r = it >> 4, c = it & 15;
        uint32_t off = (uint32_t)r * 256 + ((uint32_t)(c ^ (r & 7)) << 4);
        CP_ASYNC16(sb + off, (const void*)(g_yf + (size_t)(mbase + r) * C_ + c * 8));
        CP_ASYNC16(sb + BOF + off, (const void*)(g_wph + (size_t)r * C_ + c * 8));
    }
    CP_COMMIT();
    CP_WAIT0();
    __syncthreads();

    const int rowA0 = m0 + (grp & 1) * 8 + lr;
    const int rowB0 = n0 + (grp >> 1) * 8 + lr;
    const int chA = grp >> 1;
    const int chB = grp & 1;

    float acc[2][8][4];
#pragma unroll
    for (int mt = 0; mt < 2; mt++)
#pragma unroll
        for (int nt = 0; nt < 8; nt++)
#pragma unroll
            for (int j = 0; j < 4; j++) acc[mt][nt][j] = 0.f;

#pragma unroll
    for (int ks = 0; ks < 8; ks++) {
        const int kc = ks * 2;
        uint32_t a[2][4];
#pragma unroll
        for (int mt = 0; mt < 2; mt++) {
            int row = rowA0 + mt * 16, ch = kc + chA;
            uint32_t ad = sb + (uint32_t)row * 256 + ((uint32_t)(ch ^ (row & 7)) << 4);
            LDSM_X4(a[mt][0], a[mt][1], a[mt][2], a[mt][3], ad);
        }
        uint32_t b[4][4];
#pragma unroll
        for (int np = 0; np < 4; np++) {
            int row = rowB0 + np * 16, ch = kc + chB;
            uint32_t bd = sb + BOF + (uint32_t)row * 256 + ((uint32_t)(ch ^ (row & 7)) << 4);
            LDSM_X4(b[np][0], b[np][1], b[np][2], b[np][3], bd);
        }
#pragma unroll
        for (int mt = 0; mt < 2; mt++)
#pragma unroll
            for (int nt = 0; nt < 8; nt++)
                MMA_F16(acc[mt][nt], a[mt],
                        b[nt >> 1][(nt & 1) * 2], b[nt >> 1][(nt & 1) * 2 + 1]);
    }

#pragma unroll
    for (int mt = 0; mt < 2; mt++) {
        int r0 = mbase + m0 + mt * 16 + (lane >> 2);
#pragma unroll
        for (int nt = 0; nt < 8; nt++) {
            int c0 = n0 + nt * 8 + (lane & 3) * 2;
            *(float2*)(out0 + (size_t)r0 * C_ + c0) =
                make_float2(acc[mt][nt][0], acc[mt][nt][1]);
            *(float2*)(out0 + (size_t)(r0 + 8) * C_ + c0) =
                make_float2(acc[mt][nt][2], acc[mt][nt][3]);
        }
    }
}

// ---- stream/event infrastructure (created once at load; no device mem) -----
static cudaStream_t g_s2;
static cudaEvent_t g_e1, g_e2;
static struct SInit {
    SInit() {
        cudaStreamCreateWithFlags(&g_s2, cudaStreamNonBlocking);
        cudaEventCreateWithFlags(&g_e1, cudaEventDisableTiming);
        cudaEventCreateWithFlags(&g_e2, cudaEventDisableTiming);
    }
} g_sinit;

// ---- launch ------------------------------------------------------------------
extern "C" void kernel_launch(void* const* d_in, const int* in_sizes, int n_in,
                              void* d_out, int out_size) {
    const float* x      = (const float*)d_in[0];
    const float* w_qkv  = (const float*)d_in[1];
    const float* w_v    = (const float*)d_in[2];
    const float* w_proj = (const float*)d_in[3];
    float* out = (float*)d_out;

    const int ATT_SMEM  = 16384 + 64 * RAWS * 4;   // 115712
    const int VAL_SMEM  = 98304;
    const int PROJ_SMEM = 65536;
    const int FOLD_SMEM = 70400;                   // 2x25600 U + 2x9600 att
    cudaFuncSetAttribute(gemm_att_f16,  cudaFuncAttributeMaxDynamicSharedMemorySize, ATT_SMEM);
    cudaFuncSetAttribute(gemm_val_f16,  cudaFuncAttributeMaxDynamicSharedMemorySize, VAL_SMEM);
    cudaFuncSetAttribute(gemm_proj_f16, cudaFuncAttributeMaxDynamicSharedMemorySize, PROJ_SMEM);
    cudaFuncSetAttribute(fold_kernel,   cudaFuncAttributeMaxDynamicSharedMemorySize, FOLD_SMEM);

    const int NTOT = NX + NWV + NWP + NWQ;
    cvt_all_kernel<<<(NTOT + 255) / 256, 256>>>(x, w_v, w_proj, w_qkv);

    // fork: att on side stream, val on main stream (independent; both feed fold)
    cudaEventRecord(g_e1, 0);
    cudaStreamWaitEvent(g_s2, g_e1, 0);
    gemm_att_f16<<<NPIX / 64, 256, ATT_SMEM, g_s2>>>();
    cudaEventRecord(g_e2, g_s2);

    gemm_val_f16<<<NPIX / 128, 256, VAL_SMEM>>>();

    cudaStreamWaitEvent(0, g_e2, 0);   // join
    fold_kernel<<<NB * 256, 256, FOLD_SMEM>>>();

    gemm_proj_f16<<<NPIX / 128, 256, PROJ_SMEM>>>(out);
}